// round 1
// baseline (speedup 1.0000x reference)
#include <cuda_runtime.h>
#include <cuda_bf16.h>
#include <cstddef>

// Problem constants
#define BATCH 2
#define LEN   1024
#define DM    1024
#define DI    2048
#define NST   16
#define KCONV 4
#define RRANK 64
#define XDBL_W 96   // R + 2N

// ---------------- scratch (static device arrays; no allocation) -------------
__device__ float g_xz[BATCH * LEN * 2 * DI];   // (2048, 4096)
__device__ float g_xconv[BATCH * LEN * DI];    // (2048, 2048)
__device__ float g_xdbl[BATCH * LEN * XDBL_W]; // (2048, 96)
__device__ float g_dt[BATCH * LEN * DI];       // (2048, 2048)
__device__ float g_y[BATCH * LEN * DI];        // (2048, 2048)

// ---------------- generic tiled fp32 GEMM: C = A @ B (+bias, +act) ----------
// A: (M,K) row-major lda, B: (K,N) row-major ldb, C: (M,N) row-major ldc
// Assumes M % 128 == 0 and K % 16 == 0 (true for all calls here). N guarded.
#define BM 128
#define BN 128
#define BKT 16
#define TM 8
#define TN 8

__global__ __launch_bounds__(256) void sgemm_kernel(
    int M, int N, int K,
    const float* __restrict__ A, int lda,
    const float* __restrict__ B, int ldb,
    float* __restrict__ C, int ldc,
    const float* __restrict__ bias, int act)
{
    __shared__ float As[BKT][BM];
    __shared__ float Bs[BKT][BN];
    const int tid = threadIdx.x;
    const int bm = blockIdx.y * BM;
    const int bn = blockIdx.x * BN;
    const int tx = tid & 15;       // 16 cols of threads
    const int ty = tid >> 4;       // 16 rows of threads
    const int row0 = ty * TM;
    const int col0 = tx * TN;

    float acc[TM][TN];
#pragma unroll
    for (int i = 0; i < TM; i++)
#pragma unroll
        for (int j = 0; j < TN; j++) acc[i][j] = 0.f;

    for (int k0 = 0; k0 < K; k0 += BKT) {
        // Load A tile (BM x BKT): thread i -> (m = i/16, k = i%16)
#pragma unroll
        for (int i = tid; i < BM * BKT; i += 256) {
            int m = i >> 4;
            int k = i & 15;
            As[k][m] = A[(size_t)(bm + m) * lda + (k0 + k)];
        }
        // Load B tile (BKT x BN): thread i -> (k = i/128, n = i%128), coalesced
#pragma unroll
        for (int i = tid; i < BKT * BN; i += 256) {
            int k = i >> 7;
            int n = i & 127;
            int gn = bn + n;
            Bs[k][n] = (gn < N) ? B[(size_t)(k0 + k) * ldb + gn] : 0.f;
        }
        __syncthreads();

#pragma unroll
        for (int k = 0; k < BKT; k++) {
            float a[TM], bf[TN];
#pragma unroll
            for (int i = 0; i < TM; i++) a[i] = As[k][row0 + i];
#pragma unroll
            for (int j = 0; j < TN; j++) bf[j] = Bs[k][col0 + j];
#pragma unroll
            for (int i = 0; i < TM; i++)
#pragma unroll
                for (int j = 0; j < TN; j++)
                    acc[i][j] = fmaf(a[i], bf[j], acc[i][j]);
        }
        __syncthreads();
    }

#pragma unroll
    for (int i = 0; i < TM; i++) {
        int gm = bm + row0 + i;
#pragma unroll
        for (int j = 0; j < TN; j++) {
            int gn = bn + col0 + j;
            if (gn < N) {
                float v = acc[i][j];
                if (bias) v += bias[gn];
                if (act == 1) { // softplus
                    v = (v > 20.f) ? v : log1pf(__expf(v));
                }
                C[(size_t)gm * ldc + gn] = v;
            }
        }
    }
}

// ---------------- causal depthwise conv1d + SiLU ----------------------------
__global__ void conv_silu_kernel(const float* __restrict__ conv_w,
                                 const float* __restrict__ conv_b)
{
    int idx = blockIdx.x * blockDim.x + threadIdx.x; // over B*L*DI
    if (idx >= BATCH * LEN * DI) return;
    int d = idx & (DI - 1);
    int l = (idx >> 11) & (LEN - 1);
    int b = idx >> 21;
    float acc = conv_b[d];
#pragma unroll
    for (int j = 0; j < KCONV; j++) {
        int ll = l - (KCONV - 1) + j;
        if (ll >= 0)
            acc = fmaf(conv_w[d * KCONV + j],
                       g_xz[((size_t)(b * LEN + ll)) * (2 * DI) + d], acc);
    }
    acc = acc / (1.f + __expf(-acc)); // SiLU
    g_xconv[idx] = acc;
}

// ---------------- conv cache output -----------------------------------------
__global__ void conv_cache_kernel(float* __restrict__ cc)
{
    int idx = blockIdx.x * blockDim.x + threadIdx.x; // B*DI*K
    if (idx >= BATCH * DI * KCONV) return;
    int j = idx & (KCONV - 1);
    int d = (idx >> 2) & (DI - 1);
    int b = idx >> 13;
    cc[idx] = g_xz[((size_t)(b * LEN + (LEN - KCONV + j))) * (2 * DI) + d];
}

// ---------------- selective scan (sequential over L) ------------------------
// One thread per (b, d, n): 65536 threads total. 16-lane groups reduce over n.
// Fused epilogue: y = (scan_y + D*u) * silu(z) written directly to g_y.
__global__ __launch_bounds__(256) void scan_kernel(
    const float* __restrict__ A_log,
    const float* __restrict__ D_param,
    float* __restrict__ h_final)
{
    const int tid = threadIdx.x;
    const int gc = blockIdx.x * 16 + (tid >> 4); // global channel 0..4095
    const int n = tid & 15;
    const int b = gc >> 11;
    const int d = gc & (DI - 1);

    const float Acoef = -__expf(A_log[d * NST + n]);
    const float Dv = D_param[d];
    float h = 0.f;

    const size_t base = (size_t)b * LEN;
    // prefetch l = 0
    float dt_c = g_dt[base * DI + d];
    float u_c  = g_xconv[base * DI + d];
    float B_c  = g_xdbl[base * XDBL_W + RRANK + n];
    float C_c  = g_xdbl[base * XDBL_W + RRANK + NST + n];

    for (int l = 0; l < LEN; l++) {
        float dt_n = 0.f, u_n = 0.f, B_n = 0.f, C_n = 0.f;
        if (l + 1 < LEN) {
            size_t r = base + l + 1;
            dt_n = g_dt[r * DI + d];
            u_n  = g_xconv[r * DI + d];
            B_n  = g_xdbl[r * XDBL_W + RRANK + n];
            C_n  = g_xdbl[r * XDBL_W + RRANK + NST + n];
        }
        float abar = __expf(dt_c * Acoef);
        h = fmaf(abar, h, dt_c * B_c * u_c);
        float v = h * C_c;
#pragma unroll
        for (int off = 8; off; off >>= 1)
            v += __shfl_xor_sync(0xffffffffu, v, off);
        if (n == 0) {
            size_t r = base + l;
            float zv = g_xz[r * (2 * DI) + DI + d];
            float sil = zv / (1.f + __expf(-zv));
            g_y[r * DI + d] = (v + Dv * u_c) * sil;
        }
        dt_c = dt_n; u_c = u_n; B_c = B_n; C_c = C_n;
    }
    h_final[((size_t)b * DI + d) * NST + n] = h;
}

// ---------------- launch -----------------------------------------------------
extern "C" void kernel_launch(void* const* d_in, const int* in_sizes, int n_in,
                              void* d_out, int out_size)
{
    const float* x       = (const float*)d_in[0];
    const float* W_in    = (const float*)d_in[1];
    const float* conv_w  = (const float*)d_in[2];
    const float* conv_b  = (const float*)d_in[3];
    const float* W_x     = (const float*)d_in[4];
    const float* W_dt    = (const float*)d_in[5];
    const float* b_dt    = (const float*)d_in[6];
    const float* A_log   = (const float*)d_in[7];
    const float* D_param = (const float*)d_in[8];
    const float* W_out   = (const float*)d_in[9];

    float* out_f = (float*)d_out;
    float* out_main  = out_f;                                   // (2,1024,1024)
    float* out_hfin  = out_f + BATCH * LEN * DM;                // (2,2048,16)
    float* out_cache = out_hfin + BATCH * DI * NST;             // (2,2048,4)

    float *xz, *xconv, *xdbl, *dt, *y;
    cudaGetSymbolAddress((void**)&xz, g_xz);
    cudaGetSymbolAddress((void**)&xconv, g_xconv);
    cudaGetSymbolAddress((void**)&xdbl, g_xdbl);
    cudaGetSymbolAddress((void**)&dt, g_dt);
    cudaGetSymbolAddress((void**)&y, g_y);

    const int M = BATCH * LEN; // 2048

    // 1) xz = x @ W_in   (2048 x 4096 x 1024)
    {
        dim3 grid((2 * DI + BN - 1) / BN, M / BM);
        sgemm_kernel<<<grid, 256>>>(M, 2 * DI, DM, x, DM, W_in, 2 * DI,
                                    xz, 2 * DI, nullptr, 0);
    }
    // 2) conv + silu
    {
        int tot = BATCH * LEN * DI;
        conv_silu_kernel<<<(tot + 255) / 256, 256>>>(conv_w, conv_b);
    }
    // 3) conv cache output
    {
        int tot = BATCH * DI * KCONV;
        conv_cache_kernel<<<(tot + 255) / 256, 256>>>(out_cache);
    }
    // 4) x_dbl = x_conv @ W_x   (2048 x 96 x 2048)
    {
        dim3 grid((XDBL_W + BN - 1) / BN, M / BM);
        sgemm_kernel<<<grid, 256>>>(M, XDBL_W, DI, xconv, DI, W_x, XDBL_W,
                                    xdbl, XDBL_W, nullptr, 0);
    }
    // 5) dt = softplus(dt_low @ W_dt + b_dt)   (2048 x 2048 x 64)
    {
        dim3 grid((DI + BN - 1) / BN, M / BM);
        sgemm_kernel<<<grid, 256>>>(M, DI, RRANK, xdbl, XDBL_W, W_dt, DI,
                                    dt, DI, b_dt, 1);
    }
    // 6) selective scan (fused D-skip + silu(z) gate) -> g_y, h_final
    {
        scan_kernel<<<(BATCH * DI) / 16, 256>>>(A_log, D_param, out_hfin);
    }
    // 7) out = y @ W_out   (2048 x 1024 x 2048)
    {
        dim3 grid((DM + BN - 1) / BN, M / BM);
        sgemm_kernel<<<grid, 256>>>(M, DM, DI, y, DI, W_out, DM,
                                    out_main, DM, nullptr, 0);
    }
}

// round 2
// speedup vs baseline: 2.0486x; 2.0486x over previous
#include <cuda_runtime.h>
#include <cuda_bf16.h>
#include <cstddef>

// Problem constants
#define BATCH 2
#define LEN   1024
#define DM    1024
#define DI    2048
#define NST   16
#define KCONV 4
#define RRANK 64
#define XDBL_W 96   // R + 2N

// ---------------- scratch (static device arrays; no allocation) -------------
__device__ __align__(256) float g_xz[BATCH * LEN * 2 * DI];    // (2048, 4096)
__device__ __align__(256) float g_xconv[BATCH * LEN * DI];     // (2048, 2048)
__device__ __align__(256) float g_xdbl[BATCH * LEN * XDBL_W];  // (2048, 96)
__device__ __align__(256) float g_xdbl_part[8 * BATCH * LEN * XDBL_W]; // split-K partials
__device__ __align__(256) float g_dt[BATCH * LEN * DI];        // (2048, 2048)
__device__ __align__(256) float g_y[BATCH * LEN * DI];         // (2048, 2048)

// ============================================================================
// TF32 tensor-core GEMM: C(M,N) = A(M,K) @ B(K,N), all row-major.
// Requires M%128==0, N%128==0, K%16==0 (true for GEMM1/3/4 here).
// ACT: 0 = none, 1 = bias + softplus
// ============================================================================
#define TBM 128
#define TBN 128
#define TBK 16
#define SA  20    // As row stride in words (pad 16->20: conflict-free frag loads)
#define SB  136   // Bs row stride in words (pad 128->136: conflict-free)

__device__ __forceinline__ unsigned f2tf32(float f) {
    unsigned r;
    asm("cvt.rna.tf32.f32 %0, %1;" : "=r"(r) : "f"(f));
    return r;
}

__device__ __forceinline__ void mma_tf32(float c[4],
                                         unsigned a0, unsigned a1, unsigned a2, unsigned a3,
                                         unsigned b0, unsigned b1) {
    asm volatile(
        "mma.sync.aligned.m16n8k8.row.col.f32.tf32.tf32.f32 "
        "{%0,%1,%2,%3}, {%4,%5,%6,%7}, {%8,%9}, {%0,%1,%2,%3};"
        : "+f"(c[0]), "+f"(c[1]), "+f"(c[2]), "+f"(c[3])
        : "r"(a0), "r"(a1), "r"(a2), "r"(a3), "r"(b0), "r"(b1));
}

template <int ACT>
__global__ __launch_bounds__(256, 2) void tf32_gemm(
    int M, int N, int K,
    const float* __restrict__ A, int lda,
    const float* __restrict__ B, int ldb,
    float* __restrict__ C, int ldc,
    const float* __restrict__ bias)
{
    __shared__ unsigned As[TBM * SA];
    __shared__ unsigned Bs[TBK * SB];

    const int tid  = threadIdx.x;
    const int wid  = tid >> 5;
    const int lane = tid & 31;
    const int g    = lane >> 2;   // group id (0..7)
    const int tig  = lane & 3;    // thread in group (0..3)
    const int bm   = blockIdx.y * TBM;
    const int bn   = blockIdx.x * TBN;
    const int wm   = (wid >> 2) * 64;   // warp m offset (0 or 64)
    const int wn   = (wid & 3) * 32;    // warp n offset (0..96)

    float acc[4][4][4];
#pragma unroll
    for (int mt = 0; mt < 4; mt++)
#pragma unroll
        for (int nt = 0; nt < 4; nt++)
#pragma unroll
            for (int i = 0; i < 4; i++) acc[mt][nt][i] = 0.f;

    // Global load mapping
    const int ar = tid >> 2;          // A row (0..63), also +64
    const int ac = (tid & 3) * 4;     // A col (float4)
    const int bk = tid >> 5;          // B row (0..7), also +8
    const int bc = (tid & 31) * 4;    // B col (float4)

    const float* Ap0 = A + (size_t)(bm + ar) * lda + ac;
    const float* Ap1 = A + (size_t)(bm + ar + 64) * lda + ac;
    const float* Bp0 = B + (size_t)bk * ldb + bn + bc;
    const float* Bp1 = B + (size_t)(bk + 8) * ldb + bn + bc;

    float4 a0r, a1r, b0r, b1r;

#define LOADG(K0)                                                     \
    do {                                                              \
        a0r = *(const float4*)(Ap0 + (K0));                           \
        a1r = *(const float4*)(Ap1 + (K0));                           \
        b0r = *(const float4*)(Bp0 + (size_t)(K0) * ldb);             \
        b1r = *(const float4*)(Bp1 + (size_t)(K0) * ldb);             \
    } while (0)

#define STORES()                                                      \
    do {                                                              \
        unsigned* ap = &As[ar * SA + ac];                             \
        ap[0] = f2tf32(a0r.x); ap[1] = f2tf32(a0r.y);                 \
        ap[2] = f2tf32(a0r.z); ap[3] = f2tf32(a0r.w);                 \
        unsigned* ap2 = &As[(ar + 64) * SA + ac];                     \
        ap2[0] = f2tf32(a1r.x); ap2[1] = f2tf32(a1r.y);               \
        ap2[2] = f2tf32(a1r.z); ap2[3] = f2tf32(a1r.w);               \
        unsigned* bp = &Bs[bk * SB + bc];                             \
        bp[0] = f2tf32(b0r.x); bp[1] = f2tf32(b0r.y);                 \
        bp[2] = f2tf32(b0r.z); bp[3] = f2tf32(b0r.w);                 \
        unsigned* bp2 = &Bs[(bk + 8) * SB + bc];                      \
        bp2[0] = f2tf32(b1r.x); bp2[1] = f2tf32(b1r.y);               \
        bp2[2] = f2tf32(b1r.z); bp2[3] = f2tf32(b1r.w);               \
    } while (0)

#define COMPUTE()                                                              \
    do {                                                                       \
        _Pragma("unroll")                                                      \
        for (int kk = 0; kk < TBK; kk += 8) {                                  \
            unsigned bf[4][2];                                                 \
            _Pragma("unroll")                                                  \
            for (int nt = 0; nt < 4; nt++) {                                   \
                bf[nt][0] = Bs[(kk + tig) * SB + wn + nt * 8 + g];             \
                bf[nt][1] = Bs[(kk + tig + 4) * SB + wn + nt * 8 + g];         \
            }                                                                  \
            _Pragma("unroll")                                                  \
            for (int mt = 0; mt < 4; mt++) {                                   \
                int row = wm + mt * 16 + g;                                    \
                unsigned a0 = As[row * SA + kk + tig];                         \
                unsigned a1 = As[(row + 8) * SA + kk + tig];                   \
                unsigned a2 = As[row * SA + kk + tig + 4];                     \
                unsigned a3 = As[(row + 8) * SA + kk + tig + 4];               \
                _Pragma("unroll")                                              \
                for (int nt = 0; nt < 4; nt++)                                 \
                    mma_tf32(acc[mt][nt], a0, a1, a2, a3, bf[nt][0], bf[nt][1]);\
            }                                                                  \
        }                                                                      \
    } while (0)

    const int nk = K / TBK;
    LOADG(0);
    STORES();
    __syncthreads();
    for (int kt = 1; kt < nk; kt++) {
        LOADG(kt * TBK);
        COMPUTE();
        __syncthreads();
        STORES();
        __syncthreads();
    }
    COMPUTE();

    // Epilogue
#pragma unroll
    for (int mt = 0; mt < 4; mt++) {
#pragma unroll
        for (int nt = 0; nt < 4; nt++) {
            int r0 = bm + wm + mt * 16 + g;
            int c0 = bn + wn + nt * 8 + tig * 2;
            float v0 = acc[mt][nt][0], v1 = acc[mt][nt][1];
            float v2 = acc[mt][nt][2], v3 = acc[mt][nt][3];
            if (ACT == 1) {
                v0 += bias[c0];     v1 += bias[c0 + 1];
                v2 += bias[c0];     v3 += bias[c0 + 1];
                v0 = (v0 > 20.f) ? v0 : log1pf(__expf(v0));
                v1 = (v1 > 20.f) ? v1 : log1pf(__expf(v1));
                v2 = (v2 > 20.f) ? v2 : log1pf(__expf(v2));
                v3 = (v3 > 20.f) ? v3 : log1pf(__expf(v3));
            }
            float2 p01 = make_float2(v0, v1);
            float2 p23 = make_float2(v2, v3);
            *(float2*)&C[(size_t)r0 * ldc + c0] = p01;
            *(float2*)&C[(size_t)(r0 + 8) * ldc + c0] = p23;
        }
    }
#undef LOADG
#undef STORES
#undef COMPUTE
}

// ============================================================================
// GEMM2 (x_dbl = x_conv @ W_x), N=96, K=2048: split-K fp32, partials + reduce
// ============================================================================
#define G2_BM 64
#define G2_BK 16
#define G2_KS 8     // K splits
#define G2_KC (DI / G2_KS)  // 256 per split

__global__ __launch_bounds__(256) void gemm2_partial(const float* __restrict__ Wx)
{
    __shared__ float As2[G2_BK][G2_BM];
    __shared__ float Bs2[G2_BK][XDBL_W];
    const int tid = threadIdx.x;
    const int tx = tid & 15;   // 16 col-threads -> 6 cols each
    const int ty = tid >> 4;   // 16 row-threads -> 4 rows each
    const int ks = blockIdx.x;
    const int bm = blockIdx.y * G2_BM;
    const int kbeg = ks * G2_KC;

    float acc[4][6];
#pragma unroll
    for (int i = 0; i < 4; i++)
#pragma unroll
        for (int j = 0; j < 6; j++) acc[i][j] = 0.f;

    for (int k0 = kbeg; k0 < kbeg + G2_KC; k0 += G2_BK) {
#pragma unroll
        for (int i = tid; i < G2_BM * G2_BK; i += 256) {
            int m = i >> 4, k = i & 15;
            As2[k][m] = g_xconv[(size_t)(bm + m) * DI + k0 + k];
        }
#pragma unroll
        for (int i = tid; i < G2_BK * XDBL_W; i += 256) {
            int k = i / XDBL_W, n = i % XDBL_W;
            Bs2[k][n] = Wx[(size_t)(k0 + k) * XDBL_W + n];
        }
        __syncthreads();
#pragma unroll
        for (int k = 0; k < G2_BK; k++) {
            float a[4], b[6];
#pragma unroll
            for (int i = 0; i < 4; i++) a[i] = As2[k][ty * 4 + i];
#pragma unroll
            for (int j = 0; j < 6; j++) b[j] = Bs2[k][tx * 6 + j];
#pragma unroll
            for (int i = 0; i < 4; i++)
#pragma unroll
                for (int j = 0; j < 6; j++)
                    acc[i][j] = fmaf(a[i], b[j], acc[i][j]);
        }
        __syncthreads();
    }
#pragma unroll
    for (int i = 0; i < 4; i++)
#pragma unroll
        for (int j = 0; j < 6; j++)
            g_xdbl_part[((size_t)ks * (BATCH * LEN) + bm + ty * 4 + i) * XDBL_W
                        + tx * 6 + j] = acc[i][j];
}

__global__ void xdbl_reduce_kernel()
{
    int i = blockIdx.x * blockDim.x + threadIdx.x;
    if (i >= BATCH * LEN * XDBL_W) return;
    float s = 0.f;
#pragma unroll
    for (int p = 0; p < G2_KS; p++)
        s += g_xdbl_part[(size_t)p * (BATCH * LEN * XDBL_W) + i];
    g_xdbl[i] = s;
}

// ---------------- causal depthwise conv1d + SiLU ----------------------------
__global__ void conv_silu_kernel(const float* __restrict__ conv_w,
                                 const float* __restrict__ conv_b)
{
    int idx = blockIdx.x * blockDim.x + threadIdx.x; // over B*L*DI
    if (idx >= BATCH * LEN * DI) return;
    int d = idx & (DI - 1);
    int l = (idx >> 11) & (LEN - 1);
    int b = idx >> 21;
    float acc = conv_b[d];
#pragma unroll
    for (int j = 0; j < KCONV; j++) {
        int ll = l - (KCONV - 1) + j;
        if (ll >= 0)
            acc = fmaf(conv_w[d * KCONV + j],
                       g_xz[((size_t)(b * LEN + ll)) * (2 * DI) + d], acc);
    }
    acc = acc / (1.f + __expf(-acc)); // SiLU
    g_xconv[idx] = acc;
}

// ---------------- conv cache output -----------------------------------------
__global__ void conv_cache_kernel(float* __restrict__ cc)
{
    int idx = blockIdx.x * blockDim.x + threadIdx.x; // B*DI*K
    if (idx >= BATCH * DI * KCONV) return;
    int j = idx & (KCONV - 1);
    int d = (idx >> 2) & (DI - 1);
    int b = idx >> 13;
    cc[idx] = g_xz[((size_t)(b * LEN + (LEN - KCONV + j))) * (2 * DI) + d];
}

// ---------------- selective scan (sequential over L) ------------------------
__global__ __launch_bounds__(256) void scan_kernel(
    const float* __restrict__ A_log,
    const float* __restrict__ D_param,
    float* __restrict__ h_final)
{
    const int tid = threadIdx.x;
    const int gc = blockIdx.x * 16 + (tid >> 4); // global channel 0..4095
    const int n = tid & 15;
    const int b = gc >> 11;
    const int d = gc & (DI - 1);

    const float Acoef = -__expf(A_log[d * NST + n]);
    const float Dv = D_param[d];
    float h = 0.f;

    const size_t base = (size_t)b * LEN;
    float dt_c = g_dt[base * DI + d];
    float u_c  = g_xconv[base * DI + d];
    float B_c  = g_xdbl[base * XDBL_W + RRANK + n];
    float C_c  = g_xdbl[base * XDBL_W + RRANK + NST + n];

    for (int l = 0; l < LEN; l++) {
        float dt_n = 0.f, u_n = 0.f, B_n = 0.f, C_n = 0.f;
        if (l + 1 < LEN) {
            size_t r = base + l + 1;
            dt_n = g_dt[r * DI + d];
            u_n  = g_xconv[r * DI + d];
            B_n  = g_xdbl[r * XDBL_W + RRANK + n];
            C_n  = g_xdbl[r * XDBL_W + RRANK + NST + n];
        }
        float abar = __expf(dt_c * Acoef);
        h = fmaf(abar, h, dt_c * B_c * u_c);
        float v = h * C_c;
#pragma unroll
        for (int off = 8; off; off >>= 1)
            v += __shfl_xor_sync(0xffffffffu, v, off);
        if (n == 0) {
            size_t r = base + l;
            float zv = g_xz[r * (2 * DI) + DI + d];
            float sil = zv / (1.f + __expf(-zv));
            g_y[r * DI + d] = (v + Dv * u_c) * sil;
        }
        dt_c = dt_n; u_c = u_n; B_c = B_n; C_c = C_n;
    }
    h_final[((size_t)b * DI + d) * NST + n] = h;
}

// ---------------- launch -----------------------------------------------------
extern "C" void kernel_launch(void* const* d_in, const int* in_sizes, int n_in,
                              void* d_out, int out_size)
{
    const float* x       = (const float*)d_in[0];
    const float* W_in    = (const float*)d_in[1];
    const float* conv_w  = (const float*)d_in[2];
    const float* conv_b  = (const float*)d_in[3];
    const float* W_x     = (const float*)d_in[4];
    const float* W_dt    = (const float*)d_in[5];
    const float* b_dt    = (const float*)d_in[6];
    const float* A_log   = (const float*)d_in[7];
    const float* D_param = (const float*)d_in[8];
    const float* W_out   = (const float*)d_in[9];

    float* out_f = (float*)d_out;
    float* out_main  = out_f;                                   // (2,1024,1024)
    float* out_hfin  = out_f + BATCH * LEN * DM;                // (2,2048,16)
    float* out_cache = out_hfin + BATCH * DI * NST;             // (2,2048,4)

    float *xz, *xdbl, *dt, *y;
    cudaGetSymbolAddress((void**)&xz, g_xz);
    cudaGetSymbolAddress((void**)&xdbl, g_xdbl);
    cudaGetSymbolAddress((void**)&dt, g_dt);
    cudaGetSymbolAddress((void**)&y, g_y);

    const int M = BATCH * LEN; // 2048

    // 1) xz = x @ W_in   (2048 x 4096 x 1024)  [tf32 TC]
    {
        dim3 grid((2 * DI) / TBN, M / TBM);
        tf32_gemm<0><<<grid, 256>>>(M, 2 * DI, DM, x, DM, W_in, 2 * DI,
                                    xz, 2 * DI, nullptr);
    }
    // 2) conv + silu
    {
        int tot = BATCH * LEN * DI;
        conv_silu_kernel<<<(tot + 255) / 256, 256>>>(conv_w, conv_b);
    }
    // 3) conv cache output
    {
        int tot = BATCH * DI * KCONV;
        conv_cache_kernel<<<(tot + 255) / 256, 256>>>(out_cache);
    }
    // 4) x_dbl = x_conv @ W_x   (2048 x 96 x 2048)  [split-K fp32]
    {
        dim3 grid(G2_KS, M / G2_BM);  // (8, 32)
        gemm2_partial<<<grid, 256>>>(W_x);
        int tot = BATCH * LEN * XDBL_W;
        xdbl_reduce_kernel<<<(tot + 255) / 256, 256>>>();
    }
    // 5) dt = softplus(dt_low @ W_dt + b_dt)   (2048 x 2048 x 64)  [tf32 TC]
    {
        dim3 grid(DI / TBN, M / TBM);
        tf32_gemm<1><<<grid, 256>>>(M, DI, RRANK, xdbl, XDBL_W, W_dt, DI,
                                    dt, DI, b_dt);
    }
    // 6) selective scan (fused D-skip + silu(z) gate) -> g_y, h_final
    {
        scan_kernel<<<(BATCH * DI) / 16, 256>>>(A_log, D_param, out_hfin);
    }
    // 7) out = y @ W_out   (2048 x 1024 x 2048)  [tf32 TC]
    {
        dim3 grid(DM / TBN, M / TBM);
        tf32_gemm<0><<<grid, 256>>>(M, DM, DI, y, DI, W_out, DM,
                                    out_main, DM, nullptr);
    }
}

// round 3
// speedup vs baseline: 2.0863x; 1.0184x over previous
#include <cuda_runtime.h>
#include <cuda_bf16.h>
#include <cstddef>

// Problem constants
#define BATCH 2
#define LEN   1024
#define DM    1024
#define DI    2048
#define NST   16
#define KCONV 4
#define RRANK 64
#define XDBL_W 96   // R + 2N

// ---------------- scratch (static device arrays; no allocation) -------------
__device__ __align__(256) float g_xz[BATCH * LEN * 2 * DI];    // (2048, 4096)
__device__ __align__(256) float g_xconv[BATCH * LEN * DI];     // (2048, 2048)
__device__ __align__(256) float g_xdbl[BATCH * LEN * XDBL_W];  // (2048, 96)
__device__ __align__(256) float g_xdbl_part[8 * BATCH * LEN * XDBL_W]; // split-K partials
__device__ __align__(256) float g_dt[BATCH * LEN * DI];        // (2048, 2048)
__device__ __align__(256) float g_y[BATCH * LEN * DI];         // (2048, 2048)

// ============================================================================
// TF32 tensor-core GEMM: C(M,N) = A(M,K) @ B(K,N), all row-major.
// Double-buffered smem, 1 sync per k-tile, 2 CTAs/SM.
// Requires M%128==0, N%128==0, K%16==0. ACT: 0 = none, 1 = bias + softplus
// ============================================================================
#define TBM 128
#define TBN 128
#define TBK 16
#define SA  20    // As row stride in words (pad 16->20: conflict-free frag loads)
#define SB  136   // Bs row stride in words (pad 128->136: conflict-free)

__device__ __forceinline__ unsigned f2tf32(float f) {
    unsigned r;
    asm("cvt.rna.tf32.f32 %0, %1;" : "=r"(r) : "f"(f));
    return r;
}

__device__ __forceinline__ void mma_tf32(float c[4],
                                         unsigned a0, unsigned a1, unsigned a2, unsigned a3,
                                         unsigned b0, unsigned b1) {
    asm volatile(
        "mma.sync.aligned.m16n8k8.row.col.f32.tf32.tf32.f32 "
        "{%0,%1,%2,%3}, {%4,%5,%6,%7}, {%8,%9}, {%0,%1,%2,%3};"
        : "+f"(c[0]), "+f"(c[1]), "+f"(c[2]), "+f"(c[3])
        : "r"(a0), "r"(a1), "r"(a2), "r"(a3), "r"(b0), "r"(b1));
}

template <int ACT>
__global__ __launch_bounds__(256, 2) void tf32_gemm(
    int M, int N, int K,
    const float* __restrict__ A, int lda,
    const float* __restrict__ B, int ldb,
    float* __restrict__ C, int ldc,
    const float* __restrict__ bias)
{
    __shared__ unsigned As[2][TBM * SA];   // 2 x 10240 B
    __shared__ unsigned Bs[2][TBK * SB];   // 2 x 8704 B

    const int tid  = threadIdx.x;
    const int wid  = tid >> 5;
    const int lane = tid & 31;
    const int g    = lane >> 2;   // group id (0..7)
    const int tig  = lane & 3;    // thread in group (0..3)
    const int bm   = blockIdx.y * TBM;
    const int bn   = blockIdx.x * TBN;
    const int wm   = (wid >> 2) * 64;   // warp m offset (0 or 64)
    const int wn   = (wid & 3) * 32;    // warp n offset (0..96)

    float acc[4][4][4];
#pragma unroll
    for (int mt = 0; mt < 4; mt++)
#pragma unroll
        for (int nt = 0; nt < 4; nt++)
#pragma unroll
            for (int i = 0; i < 4; i++) acc[mt][nt][i] = 0.f;

    // Global load mapping
    const int ar = tid >> 2;          // A row (0..63), also +64
    const int ac = (tid & 3) * 4;     // A col (float4)
    const int bk = tid >> 5;          // B row (0..7), also +8
    const int bc = (tid & 31) * 4;    // B col (float4)

    const float* Ap0 = A + (size_t)(bm + ar) * lda + ac;
    const float* Ap1 = A + (size_t)(bm + ar + 64) * lda + ac;
    const float* Bp0 = B + (size_t)bk * ldb + bn + bc;
    const float* Bp1 = B + (size_t)(bk + 8) * ldb + bn + bc;

    float4 a0r, a1r, b0r, b1r;

#define LOADG(K0)                                                     \
    do {                                                              \
        a0r = *(const float4*)(Ap0 + (K0));                           \
        a1r = *(const float4*)(Ap1 + (K0));                           \
        b0r = *(const float4*)(Bp0 + (size_t)(K0) * ldb);             \
        b1r = *(const float4*)(Bp1 + (size_t)(K0) * ldb);             \
    } while (0)

#define STORES(BUF)                                                   \
    do {                                                              \
        unsigned* ap = &As[BUF][ar * SA + ac];                        \
        ap[0] = f2tf32(a0r.x); ap[1] = f2tf32(a0r.y);                 \
        ap[2] = f2tf32(a0r.z); ap[3] = f2tf32(a0r.w);                 \
        unsigned* ap2 = &As[BUF][(ar + 64) * SA + ac];                \
        ap2[0] = f2tf32(a1r.x); ap2[1] = f2tf32(a1r.y);               \
        ap2[2] = f2tf32(a1r.z); ap2[3] = f2tf32(a1r.w);               \
        unsigned* bp = &Bs[BUF][bk * SB + bc];                        \
        bp[0] = f2tf32(b0r.x); bp[1] = f2tf32(b0r.y);                 \
        bp[2] = f2tf32(b0r.z); bp[3] = f2tf32(b0r.w);                 \
        unsigned* bp2 = &Bs[BUF][(bk + 8) * SB + bc];                 \
        bp2[0] = f2tf32(b1r.x); bp2[1] = f2tf32(b1r.y);               \
        bp2[2] = f2tf32(b1r.z); bp2[3] = f2tf32(b1r.w);               \
    } while (0)

#define COMPUTE(BUF)                                                           \
    do {                                                                       \
        _Pragma("unroll")                                                      \
        for (int kk = 0; kk < TBK; kk += 8) {                                  \
            unsigned bf[4][2];                                                 \
            _Pragma("unroll")                                                  \
            for (int nt = 0; nt < 4; nt++) {                                   \
                bf[nt][0] = Bs[BUF][(kk + tig) * SB + wn + nt * 8 + g];        \
                bf[nt][1] = Bs[BUF][(kk + tig + 4) * SB + wn + nt * 8 + g];    \
            }                                                                  \
            _Pragma("unroll")                                                  \
            for (int mt = 0; mt < 4; mt++) {                                   \
                int row = wm + mt * 16 + g;                                    \
                unsigned a0 = As[BUF][row * SA + kk + tig];                    \
                unsigned a1 = As[BUF][(row + 8) * SA + kk + tig];              \
                unsigned a2 = As[BUF][row * SA + kk + tig + 4];                \
                unsigned a3 = As[BUF][(row + 8) * SA + kk + tig + 4];          \
                _Pragma("unroll")                                              \
                for (int nt = 0; nt < 4; nt++)                                 \
                    mma_tf32(acc[mt][nt], a0, a1, a2, a3, bf[nt][0], bf[nt][1]);\
            }                                                                  \
        }                                                                      \
    } while (0)

    const int nk = K / TBK;

    // Prologue: fill buffer 0, stage LDGs for tile 1
    LOADG(0);
    STORES(0);
    if (nk > 1) LOADG(TBK);
    __syncthreads();

    for (int kt = 0; kt < nk; kt++) {
        const int cur = kt & 1;
        COMPUTE(cur);
        if (kt + 1 < nk) {
            STORES(cur ^ 1);                  // staged regs -> other buffer
            if (kt + 2 < nk) LOADG((kt + 2) * TBK);  // prefetch next-next
            __syncthreads();
        }
    }

    // Epilogue
#pragma unroll
    for (int mt = 0; mt < 4; mt++) {
#pragma unroll
        for (int nt = 0; nt < 4; nt++) {
            int r0 = bm + wm + mt * 16 + g;
            int c0 = bn + wn + nt * 8 + tig * 2;
            float v0 = acc[mt][nt][0], v1 = acc[mt][nt][1];
            float v2 = acc[mt][nt][2], v3 = acc[mt][nt][3];
            if (ACT == 1) {
                v0 += bias[c0];     v1 += bias[c0 + 1];
                v2 += bias[c0];     v3 += bias[c0 + 1];
                v0 = (v0 > 20.f) ? v0 : log1pf(__expf(v0));
                v1 = (v1 > 20.f) ? v1 : log1pf(__expf(v1));
                v2 = (v2 > 20.f) ? v2 : log1pf(__expf(v2));
                v3 = (v3 > 20.f) ? v3 : log1pf(__expf(v3));
            }
            float2 p01 = make_float2(v0, v1);
            float2 p23 = make_float2(v2, v3);
            *(float2*)&C[(size_t)r0 * ldc + c0] = p01;
            *(float2*)&C[(size_t)(r0 + 8) * ldc + c0] = p23;
        }
    }
#undef LOADG
#undef STORES
#undef COMPUTE
}

// ============================================================================
// GEMM2 (x_dbl = x_conv @ W_x), N=96, K=2048: split-K fp32, partials + reduce
// ============================================================================
#define G2_BM 64
#define G2_BK 16
#define G2_KS 8     // K splits
#define G2_KC (DI / G2_KS)  // 256 per split

__global__ __launch_bounds__(256) void gemm2_partial(const float* __restrict__ Wx)
{
    __shared__ float As2[G2_BK][G2_BM + 1];   // +1 pad: distinct banks for STS
    __shared__ float Bs2[G2_BK][XDBL_W];
    const int tid = threadIdx.x;
    const int tx = tid & 15;   // 16 col-threads -> 6 cols each
    const int ty = tid >> 4;   // 16 row-threads -> 4 rows each
    const int ks = blockIdx.x;
    const int bm = blockIdx.y * G2_BM;
    const int kbeg = ks * G2_KC;

    float acc[4][6];
#pragma unroll
    for (int i = 0; i < 4; i++)
#pragma unroll
        for (int j = 0; j < 6; j++) acc[i][j] = 0.f;

    for (int k0 = kbeg; k0 < kbeg + G2_KC; k0 += G2_BK) {
#pragma unroll
        for (int i = tid; i < G2_BM * G2_BK; i += 256) {
            int m = i >> 4, k = i & 15;
            As2[k][m] = g_xconv[(size_t)(bm + m) * DI + k0 + k];
        }
#pragma unroll
        for (int i = tid; i < G2_BK * XDBL_W; i += 256) {
            int k = i / XDBL_W, n = i % XDBL_W;
            Bs2[k][n] = Wx[(size_t)(k0 + k) * XDBL_W + n];
        }
        __syncthreads();
#pragma unroll
        for (int k = 0; k < G2_BK; k++) {
            float a[4], b[6];
#pragma unroll
            for (int i = 0; i < 4; i++) a[i] = As2[k][ty * 4 + i];
#pragma unroll
            for (int j = 0; j < 6; j++) b[j] = Bs2[k][tx * 6 + j];
#pragma unroll
            for (int i = 0; i < 4; i++)
#pragma unroll
                for (int j = 0; j < 6; j++)
                    acc[i][j] = fmaf(a[i], b[j], acc[i][j]);
        }
        __syncthreads();
    }
#pragma unroll
    for (int i = 0; i < 4; i++)
#pragma unroll
        for (int j = 0; j < 6; j++)
            g_xdbl_part[((size_t)ks * (BATCH * LEN) + bm + ty * 4 + i) * XDBL_W
                        + tx * 6 + j] = acc[i][j];
}

__global__ void xdbl_reduce_kernel()
{
    int i = blockIdx.x * blockDim.x + threadIdx.x;
    if (i >= BATCH * LEN * XDBL_W) return;
    float s = 0.f;
#pragma unroll
    for (int p = 0; p < G2_KS; p++)
        s += g_xdbl_part[(size_t)p * (BATCH * LEN * XDBL_W) + i];
    g_xdbl[i] = s;
}

// ---------------- causal depthwise conv1d + SiLU ----------------------------
__global__ void conv_silu_kernel(const float* __restrict__ conv_w,
                                 const float* __restrict__ conv_b)
{
    int idx = blockIdx.x * blockDim.x + threadIdx.x; // over B*L*DI
    if (idx >= BATCH * LEN * DI) return;
    int d = idx & (DI - 1);
    int l = (idx >> 11) & (LEN - 1);
    int b = idx >> 21;
    float acc = conv_b[d];
#pragma unroll
    for (int j = 0; j < KCONV; j++) {
        int ll = l - (KCONV - 1) + j;
        if (ll >= 0)
            acc = fmaf(conv_w[d * KCONV + j],
                       g_xz[((size_t)(b * LEN + ll)) * (2 * DI) + d], acc);
    }
    acc = acc / (1.f + __expf(-acc)); // SiLU
    g_xconv[idx] = acc;
}

// ---------------- conv cache output -----------------------------------------
__global__ void conv_cache_kernel(float* __restrict__ cc)
{
    int idx = blockIdx.x * blockDim.x + threadIdx.x; // B*DI*K
    if (idx >= BATCH * DI * KCONV) return;
    int j = idx & (KCONV - 1);
    int d = (idx >> 2) & (DI - 1);
    int b = idx >> 13;
    cc[idx] = g_xz[((size_t)(b * LEN + (LEN - KCONV + j))) * (2 * DI) + d];
}

// ---------------- selective scan (sequential over L) ------------------------
__global__ __launch_bounds__(256) void scan_kernel(
    const float* __restrict__ A_log,
    const float* __restrict__ D_param,
    float* __restrict__ h_final)
{
    const int tid = threadIdx.x;
    const int gc = blockIdx.x * 16 + (tid >> 4); // global channel 0..4095
    const int n = tid & 15;
    const int b = gc >> 11;
    const int d = gc & (DI - 1);

    const float Acoef = -__expf(A_log[d * NST + n]);
    const float Dv = D_param[d];
    float h = 0.f;

    const size_t base = (size_t)b * LEN;
    float dt_c = g_dt[base * DI + d];
    float u_c  = g_xconv[base * DI + d];
    float B_c  = g_xdbl[base * XDBL_W + RRANK + n];
    float C_c  = g_xdbl[base * XDBL_W + RRANK + NST + n];

    for (int l = 0; l < LEN; l++) {
        float dt_n = 0.f, u_n = 0.f, B_n = 0.f, C_n = 0.f;
        if (l + 1 < LEN) {
            size_t r = base + l + 1;
            dt_n = g_dt[r * DI + d];
            u_n  = g_xconv[r * DI + d];
            B_n  = g_xdbl[r * XDBL_W + RRANK + n];
            C_n  = g_xdbl[r * XDBL_W + RRANK + NST + n];
        }
        float abar = __expf(dt_c * Acoef);
        h = fmaf(abar, h, dt_c * B_c * u_c);
        float v = h * C_c;
#pragma unroll
        for (int off = 8; off; off >>= 1)
            v += __shfl_xor_sync(0xffffffffu, v, off);
        if (n == 0) {
            size_t r = base + l;
            float zv = g_xz[r * (2 * DI) + DI + d];
            float sil = zv / (1.f + __expf(-zv));
            g_y[r * DI + d] = (v + Dv * u_c) * sil;
        }
        dt_c = dt_n; u_c = u_n; B_c = B_n; C_c = C_n;
    }
    h_final[((size_t)b * DI + d) * NST + n] = h;
}

// ---------------- launch -----------------------------------------------------
extern "C" void kernel_launch(void* const* d_in, const int* in_sizes, int n_in,
                              void* d_out, int out_size)
{
    const float* x       = (const float*)d_in[0];
    const float* W_in    = (const float*)d_in[1];
    const float* conv_w  = (const float*)d_in[2];
    const float* conv_b  = (const float*)d_in[3];
    const float* W_x     = (const float*)d_in[4];
    const float* W_dt    = (const float*)d_in[5];
    const float* b_dt    = (const float*)d_in[6];
    const float* A_log   = (const float*)d_in[7];
    const float* D_param = (const float*)d_in[8];
    const float* W_out   = (const float*)d_in[9];

    float* out_f = (float*)d_out;
    float* out_main  = out_f;                                   // (2,1024,1024)
    float* out_hfin  = out_f + BATCH * LEN * DM;                // (2,2048,16)
    float* out_cache = out_hfin + BATCH * DI * NST;             // (2,2048,4)

    float *xz, *xdbl, *dt, *y;
    cudaGetSymbolAddress((void**)&xz, g_xz);
    cudaGetSymbolAddress((void**)&xdbl, g_xdbl);
    cudaGetSymbolAddress((void**)&dt, g_dt);
    cudaGetSymbolAddress((void**)&y, g_y);

    const int M = BATCH * LEN; // 2048

    // 1) xz = x @ W_in   (2048 x 4096 x 1024)  [tf32 TC]
    {
        dim3 grid((2 * DI) / TBN, M / TBM);
        tf32_gemm<0><<<grid, 256>>>(M, 2 * DI, DM, x, DM, W_in, 2 * DI,
                                    xz, 2 * DI, nullptr);
    }
    // 2) conv + silu
    {
        int tot = BATCH * LEN * DI;
        conv_silu_kernel<<<(tot + 255) / 256, 256>>>(conv_w, conv_b);
    }
    // 3) conv cache output
    {
        int tot = BATCH * DI * KCONV;
        conv_cache_kernel<<<(tot + 255) / 256, 256>>>(out_cache);
    }
    // 4) x_dbl = x_conv @ W_x   (2048 x 96 x 2048)  [split-K fp32]
    {
        dim3 grid(G2_KS, M / G2_BM);  // (8, 32)
        gemm2_partial<<<grid, 256>>>(W_x);
        int tot = BATCH * LEN * XDBL_W;
        xdbl_reduce_kernel<<<(tot + 255) / 256, 256>>>();
    }
    // 5) dt = softplus(dt_low @ W_dt + b_dt)   (2048 x 2048 x 64)  [tf32 TC]
    {
        dim3 grid(DI / TBN, M / TBM);
        tf32_gemm<1><<<grid, 256>>>(M, DI, RRANK, xdbl, XDBL_W, W_dt, DI,
                                    dt, DI, b_dt);
    }
    // 6) selective scan (fused D-skip + silu(z) gate) -> g_y, h_final
    {
        scan_kernel<<<(BATCH * DI) / 16, 256>>>(A_log, D_param, out_hfin);
    }
    // 7) out = y @ W_out   (2048 x 1024 x 2048)  [tf32 TC]
    {
        dim3 grid(DM / TBN, M / TBM);
        tf32_gemm<0><<<grid, 256>>>(M, DM, DI, y, DI, W_out, DM,
                                    out_main, DM, nullptr);
    }
}